// round 1
// baseline (speedup 1.0000x reference)
#include <cuda_runtime.h>

// Problem constants (fixed shapes: B=2, C=3, H=320, W=480)
#define HH   320
#define WW   480
#define BB   2
#define HWP  (HH * WW)          // 153600
#define NPIX (BB * HWP)         // 307200
#define SPAN 11
#define NOFF 23
#define NOFF2 (NOFF * NOFF)     // 529

// ---------------- scratch (static device globals; no allocation) ------------
__device__ float4 g_img[NPIX];   // (r, g, b, m_dst)
__device__ float4 g_yh[NPIX];    // (yh0, yh1, yh2, w_p = src*(1-dst))
__device__ float  g_M[HWP];      // sum over batch of m_dst
__device__ int    g_act[NPIX];   // compacted linear indices of active pixels
__device__ int    g_nact;
__device__ float  g_num[NOFF2];
__device__ float  g_den[NOFF2];
__device__ float  g_ce;

// ---------------- helpers ----------------------------------------------------
__device__ __forceinline__ float warpReduceSum(float v) {
#pragma unroll
    for (int o = 16; o > 0; o >>= 1)
        v += __shfl_xor_sync(0xffffffffu, v, o);
    return v;
}

// Full-block reduction; result valid in thread 0. All threads must call it.
__device__ __forceinline__ float blockReduceSum(float v) {
    __shared__ float sh[32];
    int lane = threadIdx.x & 31;
    int wid  = threadIdx.x >> 5;
    v = warpReduceSum(v);
    if (lane == 0) sh[wid] = v;
    __syncthreads();
    int nw = (blockDim.x + 31) >> 5;
    v = (wid == 0 && lane < nw) ? sh[lane] : 0.0f;
    if (wid == 0) v = warpReduceSum(v);
    return v;
}

// ---------------- kernel 0: zero accumulators --------------------------------
__global__ void k_zero() {
    int t = threadIdx.x;
    if (t < NOFF2) g_num[t] = 0.0f;
    if (t == NOFF2)     g_ce = 0.0f;
    if (t == NOFF2 + 1) g_nact = 0;
}

// ---------------- kernel 1: softmax/CE/pack/compact ---------------------------
// One thread per (i,j); handles both batch entries.
__global__ void k_prep(const float* __restrict__ logit,
                       const float* __restrict__ image,
                       const float* __restrict__ src,
                       const float* __restrict__ dst,
                       const int*   __restrict__ tgt) {
    int idx = blockIdx.x * blockDim.x + threadIdx.x;
    float prod = 0.0f;
    if (idx < HWP) {
        float Msum = 0.0f, ceSum = 0.0f, dstSum = 0.0f;
#pragma unroll
        for (int b = 0; b < BB; b++) {
            int cb = b * 3 * HWP + idx;
            float l0 = logit[cb], l1 = logit[cb + HWP], l2 = logit[cb + 2 * HWP];
            float m  = fmaxf(l0, fmaxf(l1, l2));
            float e0 = __expf(l0 - m), e1 = __expf(l1 - m), e2 = __expf(l2 - m);
            float s  = e0 + e1 + e2;
            float inv = 1.0f / s;

            int   t  = tgt[b * HWP + idx];
            float lt = (t == 0) ? l0 : ((t == 1) ? l1 : l2);
            float ce = m + __logf(s) - lt;           // -log_softmax[target]

            float sv   = src[b * HWP + idx];
            float dv   = dst[b * HWP + idx];
            float mdst = 1.0f - dv;
            float wp   = sv * mdst;

            float i0 = image[cb], i1 = image[cb + HWP], i2 = image[cb + 2 * HWP];
            g_img[b * HWP + idx] = make_float4(i0, i1, i2, mdst);
            g_yh[b * HWP + idx]  = make_float4(e0 * inv, e1 * inv, e2 * inv, wp);

            ceSum  += ce;
            dstSum += dv;
            Msum   += mdst;

            if (wp > 0.0f) {
                int slot = atomicAdd(&g_nact, 1);
                g_act[slot] = b * HWP + idx;
            }
        }
        g_M[idx] = Msum;
        prod = ceSum * dstSum;   // per-(h,w) product of batch sums
    }
    float bs = blockReduceSum(prod);
    if (threadIdx.x == 0) atomicAdd(&g_ce, bs);
}

// ---------------- kernel 2: denominators (rectangle sums of g_M) -------------
// One block per offset d; den(d) = sum of M over the valid rectangle.
__global__ void k_den() {
    int d  = blockIdx.x;
    int dx = d / NOFF - SPAN;
    int dy = d % NOFF - SPAN;
    int r0 = (dx < 0) ? -dx : 0;
    int r1 = (dx > 0) ? HH - dx : HH;
    int c0 = (dy < 0) ? -dy : 0;
    int c1 = (dy > 0) ? WW - dy : WW;
    int cw = c1 - c0;
    int N  = (r1 - r0) * cw;
    float s = 0.0f;
    for (int t = threadIdx.x; t < N; t += blockDim.x) {
        int i = r0 + t / cw;
        int j = c0 + t % cw;
        s += g_M[i * WW + j];
    }
    float tot = blockReduceSum(s);
    if (threadIdx.x == 0) g_den[d] = tot;
}

// ---------------- kernel 3: numerators (main loop over active pixels) --------
// Thread = one compacted active pixel; loops over all 484 non-skip offsets.
// Lanes share the offset index each iteration -> warp-reduce + 1 atomic/warp.
__global__ void __launch_bounds__(256) k_num() {
    int n    = g_nact;
    int gtid = blockIdx.x * blockDim.x + threadIdx.x;
    int lane = gtid & 31;
    if ((gtid & ~31) >= n) return;            // whole warp idle -> exit

    bool act = gtid < n;
    int  p   = act ? g_act[gtid] : g_act[0];  // safe dummy for tail lanes
    int  b   = p / HWP;
    int  rem = p - b * HWP;
    int  i   = rem / WW;
    int  j   = rem - i * WW;
    int  bHW = b * HWP;

    float4 I = g_img[p];
    float4 Y = g_yh[p];
    float  wp = act ? Y.w : 0.0f;

#pragma unroll 1
    for (int dx = -SPAN; dx <= SPAN; dx++) {
        if (dx == 0) continue;
        int  qi    = i + dx;
        bool rowOk = (qi >= 0) && (qi < HH);
        int  rowBase = bHW + qi * WW;
        float kxr  = __expf((float)(dx * dx) * (-1.0f / 72.0f));
#pragma unroll
        for (int dy = -SPAN; dy <= SPAN; dy++) {
            if (dy == 0) continue;
            int   qj = j + dy;
            float c  = 0.0f;
            if (rowOk && qj >= 0 && qj < WW) {
                int    q  = rowBase + qj;
                float4 Iq = g_img[q];
                float4 Yq = g_yh[q];
                float d0 = I.x - Iq.x, d1 = I.y - Iq.y, d2 = I.z - Iq.z;
                float ssd  = d0 * d0 + d1 * d1 + d2 * d2;
                float krgb = __expf(-50.0f * ssd);                       // exp(-0.5*||diff/0.1||^2)
                float kxy  = kxr * __expf((float)(dy * dy) * (-1.0f / 72.0f));
                float dot  = Y.x * Yq.x + Y.y * Yq.y + Y.z * Yq.z;
                c = wp * (krgb + kxy) * (1.0f - dot);                    // r = 1 - <yh_p, yh_q>
            }
            c = warpReduceSum(c);
            if (lane == 0)
                atomicAdd(&g_num[(dx + SPAN) * NOFF + (dy + SPAN)], c);
        }
    }
}

// ---------------- kernel 4: finalize ------------------------------------------
__global__ void k_final(float* __restrict__ out) {
    float s = 0.0f;
    for (int d = threadIdx.x; d < NOFF2; d += blockDim.x) {
        int dx = d / NOFF - SPAN;
        int dy = d % NOFF - SPAN;
        if (dx != 0 && dy != 0) s += g_num[d] / g_den[d];
    }
    float tot = blockReduceSum(s);
    if (threadIdx.x == 0) {
        float l_ce   = g_ce * (1.0f / ((float)BB * BB * HWP));
        float l_gcrf = tot * (1.0f / (float)NOFF2);
        out[0] = l_ce + 0.15f * l_gcrf;
    }
}

// ---------------- launch --------------------------------------------------------
extern "C" void kernel_launch(void* const* d_in, const int* in_sizes, int n_in,
                              void* d_out, int out_size) {
    const float* logit = (const float*)d_in[0];
    const float* image = (const float*)d_in[1];
    const float* srcm  = (const float*)d_in[2];
    const float* dstm  = (const float*)d_in[3];
    const int*   tgt   = (const int*)d_in[4];
    float* out = (float*)d_out;

    k_zero<<<1, NOFF2 + 32>>>();
    k_prep<<<HWP / 256, 256>>>(logit, image, srcm, dstm, tgt);
    k_den<<<NOFF2, 256>>>();
    k_num<<<NPIX / 256, 256>>>();
    k_final<<<1, 256>>>(out);
}